// round 2
// baseline (speedup 1.0000x reference)
#include <cuda_runtime.h>

#define NN   50000
#define EE   800000
#define CIN  64
#define CH   128
#define COUT 2
#define GG   512

// ---------------- scratch (static device globals; no allocation) -------------
__device__ float g_hA[NN * CH];
__device__ float g_hB[NN * CH];
__device__ float g_agg[NN * CH];
__device__ int   g_deg[NN];
__device__ int   g_inc[NN];
__device__ int   g_rowptr[NN + 1];
__device__ int   g_cursor[NN];
__device__ int   g_col[EE];
__device__ int   g_bsum[64];
__device__ int   g_gcnt[GG];
__device__ float g_gsum[GG * CH];

// ---------------- graph preprocessing ---------------------------------------
__global__ void k_init() {
    int i = blockIdx.x * blockDim.x + threadIdx.x;
    if (i < NN) { g_deg[i] = 0; g_cursor[i] = 0; }
    if (i < GG) g_gcnt[i] = 0;
    if (i < GG * CH) g_gsum[i] = 0.f;
}

__global__ void k_count(const int* __restrict__ dst) {
    int e = blockIdx.x * blockDim.x + threadIdx.x;
    if (e < EE) atomicAdd(&g_deg[dst[e]], 1);
}

__global__ void k_scan1() {  // per-block inclusive scan of g_deg
    __shared__ int s[1024];
    int tid = threadIdx.x;
    int idx = blockIdx.x * 1024 + tid;
    int v = (idx < NN) ? g_deg[idx] : 0;
    s[tid] = v;
    __syncthreads();
    for (int off = 1; off < 1024; off <<= 1) {
        int t = (tid >= off) ? s[tid - off] : 0;
        __syncthreads();
        s[tid] += t;
        __syncthreads();
    }
    if (idx < NN) g_inc[idx] = s[tid];
    if (tid == 1023) g_bsum[blockIdx.x] = s[1023];
}

__global__ void k_scan2(int nb) {  // tiny serial exclusive scan of block sums
    if (threadIdx.x == 0 && blockIdx.x == 0) {
        int run = 0;
        for (int i = 0; i < nb; i++) { int v = g_bsum[i]; g_bsum[i] = run; run += v; }
    }
}

__global__ void k_scan3() {
    int i = blockIdx.x * blockDim.x + threadIdx.x;
    if (i < NN) g_rowptr[i + 1] = g_inc[i] + g_bsum[i >> 10];
    if (i == 0) g_rowptr[0] = 0;
}

__global__ void k_fill(const int* __restrict__ src, const int* __restrict__ dst) {
    int e = blockIdx.x * blockDim.x + threadIdx.x;
    if (e < EE) {
        int d = dst[e];
        int pos = g_rowptr[d] + atomicAdd(&g_cursor[d], 1);
        g_col[pos] = src[e];
    }
}

__global__ void k_gcnt(const int* __restrict__ batch) {
    int i = blockIdx.x * blockDim.x + threadIdx.x;
    if (i < NN) atomicAdd(&g_gcnt[batch[i]], 1);
}

// ---------------- neighbor mean aggregation ----------------------------------
template <int K>
__global__ void k_agg(const float* __restrict__ h, float* __restrict__ agg) {
    const int NPB = 256 / K;  // nodes per block
    int node = blockIdx.x * NPB + threadIdx.x / K;
    int c = threadIdx.x % K;
    if (node >= NN) return;
    int s = g_rowptr[node], e = g_rowptr[node + 1];
    float a0 = 0.f, a1 = 0.f;
    int j = s;
    for (; j + 2 <= e; j += 2) {
        int n0 = g_col[j], n1 = g_col[j + 1];
        a0 += h[(size_t)n0 * K + c];
        a1 += h[(size_t)n1 * K + c];
    }
    if (j < e) a0 += h[(size_t)g_col[j] * K + c];
    float acc = a0 + a1;
    agg[(size_t)node * K + c] = (e > s) ? acc / (float)(e - s) : 0.f;
}

// ---------------- fused dual-GEMM + bias + activation ------------------------
// out[r, 0:128] = agg[r, 0:K] @ Wl + h[r, 0:K] @ Wr + b ; act
// ACT: 0 = none, 1 = relu, 2 = leaky(0.01)
template <int K, int ACT>
__global__ void __launch_bounds__(256, 1)
k_gemm(const float* __restrict__ Xa, const float* __restrict__ Xh,
       const float* __restrict__ Wl, const float* __restrict__ Wr,
       const float* __restrict__ bias, float* __restrict__ out) {
    extern __shared__ float sm[];
    float* sWl = sm;                  // K * 128
    float* sWr = sWl + K * CH;        // K * 128
    float* sXa = sWr + K * CH;        // 64 * K
    float* sXh = sXa + 64 * K;        // 64 * K

    const int tid = threadIdx.x;
    const int row0 = blockIdx.x * 64;

    for (int i = tid; i < K * CH / 4; i += 256) {
        ((float4*)sWl)[i] = ((const float4*)Wl)[i];
        ((float4*)sWr)[i] = ((const float4*)Wr)[i];
    }
    for (int i = tid; i < 64 * K / 4; i += 256) {
        int r = i / (K / 4);
        int kq = i % (K / 4);
        int gr = row0 + r;
        float4 va = make_float4(0.f, 0.f, 0.f, 0.f);
        float4 vh = va;
        if (gr < NN) {
            va = ((const float4*)(Xa + (size_t)gr * K))[kq];
            vh = ((const float4*)(Xh + (size_t)gr * K))[kq];
        }
        ((float4*)sXa)[i] = va;
        ((float4*)sXh)[i] = vh;
    }
    __syncthreads();

    const int ty = tid >> 5;      // 0..7  -> 8 row groups of 8
    const int tx = tid & 31;      // 0..31 -> 32 col groups of 4
    const int r0 = ty * 8;
    const int c0 = tx * 4;

    float acc[8][4];
#pragma unroll
    for (int r = 0; r < 8; r++)
#pragma unroll
        for (int c = 0; c < 4; c++) acc[r][c] = 0.f;

#pragma unroll 2
    for (int k = 0; k < K; k += 4) {
        float4 a4[8], h4[8];
#pragma unroll
        for (int r = 0; r < 8; r++) {
            a4[r] = *((const float4*)&sXa[(r0 + r) * K + k]);
            h4[r] = *((const float4*)&sXh[(r0 + r) * K + k]);
        }
#pragma unroll
        for (int kk = 0; kk < 4; kk++) {
            float4 wl = *((const float4*)&sWl[(k + kk) * CH + c0]);
            float4 wr = *((const float4*)&sWr[(k + kk) * CH + c0]);
#pragma unroll
            for (int r = 0; r < 8; r++) {
                float a = (&a4[r].x)[kk];
                float hh = (&h4[r].x)[kk];
                acc[r][0] += a * wl.x; acc[r][0] += hh * wr.x;
                acc[r][1] += a * wl.y; acc[r][1] += hh * wr.y;
                acc[r][2] += a * wl.z; acc[r][2] += hh * wr.z;
                acc[r][3] += a * wl.w; acc[r][3] += hh * wr.w;
            }
        }
    }

    float4 bb = *((const float4*)&bias[c0]);
#pragma unroll
    for (int r = 0; r < 8; r++) {
        int gr = row0 + r0 + r;
        if (gr >= NN) continue;
        float v[4];
        v[0] = acc[r][0] + bb.x;
        v[1] = acc[r][1] + bb.y;
        v[2] = acc[r][2] + bb.z;
        v[3] = acc[r][3] + bb.w;
#pragma unroll
        for (int c = 0; c < 4; c++) {
            if (ACT == 1) v[c] = fmaxf(v[c], 0.f);
            else if (ACT == 2) v[c] = (v[c] > 0.f) ? v[c] : 0.01f * v[c];
        }
        *((float4*)&out[(size_t)gr * CH + c0]) = make_float4(v[0], v[1], v[2], v[3]);
    }
}

// ---------------- pooling + head ---------------------------------------------
__global__ void k_pool(const int* __restrict__ batch, const float* __restrict__ h) {
    int idx = blockIdx.x * blockDim.x + threadIdx.x;
    if (idx < NN * CH) {
        int i = idx >> 7;   // /128
        int c = idx & 127;
        atomicAdd(&g_gsum[batch[i] * CH + c], h[idx]);
    }
}

__global__ void k_head(const float* __restrict__ headW,
                       const float* __restrict__ headb,
                       float* __restrict__ out) {
    int tid = blockIdx.x * blockDim.x + threadIdx.x;
    if (tid >= GG * COUT) return;
    int g = tid >> 1;
    int o = tid & 1;
    float cnt = (float)g_gcnt[g];
    float inv = 1.f / fmaxf(cnt, 1.f);
    float acc = headb[o];
#pragma unroll 8
    for (int k = 0; k < CH; k++)
        acc += g_gsum[g * CH + k] * inv * headW[k * COUT + o];
    out[tid] = acc;
}

// ---------------- host driver -------------------------------------------------
extern "C" void kernel_launch(void* const* d_in, const int* in_sizes, int n_in,
                              void* d_out, int out_size) {
    const float* x     = (const float*)d_in[0];
    const int*   ei    = (const int*)d_in[1];
    const int*   srcp  = ei;
    const int*   dstp  = ei + EE;
    const int*   batch = (const int*)d_in[2];
    const float* Wl0   = (const float*)d_in[3];
    const float* Wr0   = (const float*)d_in[4];
    const float* b0    = (const float*)d_in[5];
    const float* Wl    = (const float*)d_in[6];
    const float* Wr    = (const float*)d_in[7];
    const float* bb    = (const float*)d_in[8];
    const float* headW = (const float*)d_in[9];
    const float* headb = (const float*)d_in[10];
    float* out = (float*)d_out;

    float *hA, *hB, *agg;
    cudaGetSymbolAddress((void**)&hA, g_hA);
    cudaGetSymbolAddress((void**)&hB, g_hB);
    cudaGetSymbolAddress((void**)&agg, g_agg);

    const int smem64  = (CIN * CH * 2 + 64 * CIN * 2) * 4;   //  98304 B
    const int smem128 = (CH * CH * 2 + 64 * CH * 2) * 4;     // 196608 B
    cudaFuncSetAttribute(k_gemm<64, 1>,  cudaFuncAttributeMaxDynamicSharedMemorySize, smem64);
    cudaFuncSetAttribute(k_gemm<128, 0>, cudaFuncAttributeMaxDynamicSharedMemorySize, smem128);
    cudaFuncSetAttribute(k_gemm<128, 1>, cudaFuncAttributeMaxDynamicSharedMemorySize, smem128);
    cudaFuncSetAttribute(k_gemm<128, 2>, cudaFuncAttributeMaxDynamicSharedMemorySize, smem128);

    // --- graph preprocessing (CSR by dst, graph sizes) ---
    k_init<<<256, 256>>>();
    k_count<<<(EE + 255) / 256, 256>>>(dstp);
    k_scan1<<<(NN + 1023) / 1024, 1024>>>();
    k_scan2<<<1, 32>>>((NN + 1023) / 1024);
    k_scan3<<<(NN + 255) / 256, 256>>>();
    k_fill<<<(EE + 255) / 256, 256>>>(srcp, dstp);
    k_gcnt<<<(NN + 255) / 256, 256>>>(batch);

    const int gemmGrid = (NN + 63) / 64;

    // --- layer 0: C_IN=64 -> 128, ReLU ---
    k_agg<64><<<(NN + 3) / 4, 256>>>(x, agg);
    k_gemm<64, 1><<<gemmGrid, 256, smem64>>>(agg, x, Wl0, Wr0, b0, hA);

    // --- layers 1..11 ---
    // global conv index ci = li+1; relu unless (ci+1)%4==0; leaky at ci=3,7; none at ci=11
    const int act[11] = {1, 1, 2, 1, 1, 1, 2, 1, 1, 1, 0};
    const float* cur = hA;
    float* nxt = hB;
    for (int li = 0; li < 11; li++) {
        k_agg<128><<<(NN + 1) / 2, 256>>>(cur, agg);
        const float* wl = Wl + (size_t)li * CH * CH;
        const float* wr = Wr + (size_t)li * CH * CH;
        const float* bi = bb + (size_t)li * CH;
        if (act[li] == 1)
            k_gemm<128, 1><<<gemmGrid, 256, smem128>>>(agg, cur, wl, wr, bi, nxt);
        else if (act[li] == 2)
            k_gemm<128, 2><<<gemmGrid, 256, smem128>>>(agg, cur, wl, wr, bi, nxt);
        else
            k_gemm<128, 0><<<gemmGrid, 256, smem128>>>(agg, cur, wl, wr, bi, nxt);
        const float* t = cur;
        cur = nxt;
        nxt = (float*)t;
    }

    // --- global mean pool + head ---
    k_pool<<<(NN * CH + 255) / 256, 256>>>(batch, cur);
    k_head<<<(GG * COUT + 255) / 256, 256>>>(headW, headb, out);
}

// round 4
// speedup vs baseline: 1.4356x; 1.4356x over previous
#include <cuda_runtime.h>
#include <cuda_bf16.h>
#include <cstdint>

#define NN   50000
#define EE   800000
#define CIN  64
#define CH   128
#define COUT 2
#define GG   512

#define NTILES   ((NN + 127) / 128)   // 391
#define GRID_G   148

// ---------------- scratch (static device globals; no allocation) -------------
__device__ float g_hA[NN * CH];
__device__ float g_hB[NN * CH];
__device__ float g_agg[NN * CH];
__device__ int   g_deg[NN];
__device__ int   g_inc[NN];
__device__ int   g_rowptr[NN + 1];
__device__ int   g_cursor[NN];
__device__ int   g_col[EE];
__device__ int   g_bsum[64];
__device__ int   g_gcnt[GG];
__device__ float g_gsum[GG * CH];
// pre-transposed, bf16-split weights, linear [N=128][K=256] per conv
__device__ __nv_bfloat16 g_Bhi[12 * 32768];
__device__ __nv_bfloat16 g_Blo[12 * 32768];

// ---------------- graph preprocessing ---------------------------------------
__global__ void k_init() {
    int i = blockIdx.x * blockDim.x + threadIdx.x;
    if (i < NN) { g_deg[i] = 0; g_cursor[i] = 0; }
    if (i < GG) g_gcnt[i] = 0;
    if (i < GG * CH) g_gsum[i] = 0.f;
}

__global__ void k_count(const int* __restrict__ dst) {
    int e = blockIdx.x * blockDim.x + threadIdx.x;
    if (e < EE) atomicAdd(&g_deg[dst[e]], 1);
}

__global__ void k_scan1() {
    __shared__ int s[1024];
    int tid = threadIdx.x;
    int idx = blockIdx.x * 1024 + tid;
    int v = (idx < NN) ? g_deg[idx] : 0;
    s[tid] = v;
    __syncthreads();
    for (int off = 1; off < 1024; off <<= 1) {
        int t = (tid >= off) ? s[tid - off] : 0;
        __syncthreads();
        s[tid] += t;
        __syncthreads();
    }
    if (idx < NN) g_inc[idx] = s[tid];
    if (tid == 1023) g_bsum[blockIdx.x] = s[1023];
}

__global__ void k_scan2(int nb) {
    if (threadIdx.x == 0 && blockIdx.x == 0) {
        int run = 0;
        for (int i = 0; i < nb; i++) { int v = g_bsum[i]; g_bsum[i] = run; run += v; }
    }
}

__global__ void k_scan3() {
    int i = blockIdx.x * blockDim.x + threadIdx.x;
    if (i < NN) g_rowptr[i + 1] = g_inc[i] + g_bsum[i >> 10];
    if (i == 0) g_rowptr[0] = 0;
}

__global__ void k_fill(const int* __restrict__ src, const int* __restrict__ dst) {
    int e = blockIdx.x * blockDim.x + threadIdx.x;
    if (e < EE) {
        int d = dst[e];
        int pos = g_rowptr[d] + atomicAdd(&g_cursor[d], 1);
        g_col[pos] = src[e];
    }
}

__global__ void k_gcnt(const int* __restrict__ batch) {
    int i = blockIdx.x * blockDim.x + threadIdx.x;
    if (i < NN) atomicAdd(&g_gcnt[batch[i]], 1);
}

// weight prep: transpose [K,N]->[N,K] concat [Wl | Wr], split fp32 -> bf16 hi+lo
__global__ void k_prepw(const float* __restrict__ Wl0, const float* __restrict__ Wr0,
                        const float* __restrict__ Wl, const float* __restrict__ Wr) {
    int idx = blockIdx.x * blockDim.x + threadIdx.x;
    if (idx >= 12 * 32768) return;
    int ci = idx >> 15;
    int r  = idx & 32767;
    int j  = r >> 8;      // out col (0..127) -> B row n
    int k  = r & 255;     // concat K index
    float w = 0.f;
    if (ci == 0) {
        if (k < CIN)                  w = Wl0[k * CH + j];
        else if (k >= 128 && k < 192) w = Wr0[(k - 128) * CH + j];
    } else {
        int li = ci - 1;
        if (k < 128) w = Wl[((size_t)li * CH + k) * CH + j];
        else         w = Wr[((size_t)li * CH + (k - 128)) * CH + j];
    }
    __nv_bfloat16 hi = __float2bfloat16(w);
    __nv_bfloat16 lo = __float2bfloat16(w - __bfloat162float(hi));
    g_Bhi[idx] = hi;
    g_Blo[idx] = lo;
}

// ---------------- neighbor mean aggregation ----------------------------------
template <int K>
__global__ void k_agg(const float* __restrict__ h, float* __restrict__ agg) {
    const int NPB = 256 / K;
    int node = blockIdx.x * NPB + threadIdx.x / K;
    int c = threadIdx.x % K;
    if (node >= NN) return;
    int s = g_rowptr[node], e = g_rowptr[node + 1];
    float a0 = 0.f, a1 = 0.f, a2 = 0.f, a3 = 0.f;
    int j = s;
    for (; j + 4 <= e; j += 4) {
        int n0 = g_col[j], n1 = g_col[j + 1], n2 = g_col[j + 2], n3 = g_col[j + 3];
        a0 += h[(size_t)n0 * K + c];
        a1 += h[(size_t)n1 * K + c];
        a2 += h[(size_t)n2 * K + c];
        a3 += h[(size_t)n3 * K + c];
    }
    for (; j < e; j++) a0 += h[(size_t)g_col[j] * K + c];
    float acc = (a0 + a1) + (a2 + a3);
    agg[(size_t)node * K + c] = (e > s) ? acc / (float)(e - s) : 0.f;
}

// ---------------- HMMA bf16 split-3 dual GEMM --------------------------------
// out[m, 0:128] = agg @ Wl + h @ Wr + b ; activation.
// A = [agg | h] concat K=256; D = Ahi*Bhi + Ahi*Blo + Alo*Bhi, fp32 acc.
// SMEM: B resident [128][264] bf16 (hi+lo), A chunk [128][136] bf16 (hi+lo).
#define SB_STR 264              // bf16 units (132 u32) — conflict-free frag loads
#define SA_STR 136              // bf16 units (68 u32)
#define SMO_BH 0
#define SMO_BL (128 * SB_STR * 2)                 //  67584
#define SMO_AH (2 * 128 * SB_STR * 2)             // 135168
#define SMO_AL (2 * 128 * SB_STR * 2 + 128 * SA_STR * 2)  // 169984
#define SM_TOT (2 * 128 * SB_STR * 2 + 2 * 128 * SA_STR * 2)  // 204800

__device__ __forceinline__ void mma16816(float* d, const uint32_t* a,
                                         uint32_t b0, uint32_t b1) {
    asm volatile(
        "mma.sync.aligned.m16n8k16.row.col.f32.bf16.bf16.f32 "
        "{%0,%1,%2,%3}, {%4,%5,%6,%7}, {%8,%9}, {%0,%1,%2,%3};"
        : "+f"(d[0]), "+f"(d[1]), "+f"(d[2]), "+f"(d[3])
        : "r"(a[0]), "r"(a[1]), "r"(a[2]), "r"(a[3]), "r"(b0), "r"(b1));
}

template <int KIN, int ACT>
__global__ void __launch_bounds__(256, 1)
k_hgemm(const float* __restrict__ Xa, const float* __restrict__ Xh,
        const __nv_bfloat16* __restrict__ Bhi, const __nv_bfloat16* __restrict__ Blo,
        const float* __restrict__ bias, float* __restrict__ out) {
    extern __shared__ char sm[];
    __nv_bfloat16* sBh = (__nv_bfloat16*)(sm + SMO_BH);
    __nv_bfloat16* sBl = (__nv_bfloat16*)(sm + SMO_BL);
    __nv_bfloat16* sAh = (__nv_bfloat16*)(sm + SMO_AH);
    __nv_bfloat16* sAl = (__nv_bfloat16*)(sm + SMO_AL);

    const int tid = threadIdx.x;
    const int wid = tid >> 5, lid = tid & 31;
    const int g = lid >> 2, tig = lid & 3;
    const int m0 = (wid & 3) * 32;        // warp row origin within tile
    const int n0 = (wid >> 2) * 64;       // warp col origin

    // load resident B (hi+lo) into padded SMEM
    for (int i = tid; i < 4096; i += 256) {
        int n = i >> 5, kq = i & 31;      // kq*8 bf16
        float4 vh = ((const float4*)Bhi)[i];
        float4 vl = ((const float4*)Blo)[i];
        *(float4*)&sBh[n * SB_STR + kq * 8] = vh;
        *(float4*)&sBl[n * SB_STR + kq * 8] = vl;
    }

    const uint32_t* uBh = (const uint32_t*)sBh;
    const uint32_t* uBl = (const uint32_t*)sBl;
    const uint32_t* uAh = (const uint32_t*)sAh;
    const uint32_t* uAl = (const uint32_t*)sAl;
    constexpr int KSTEPS = (KIN == 64) ? 4 : 8;   // skip zero-padded K half

    for (int t = blockIdx.x; t < NTILES; t += GRID_G) {
        const int row0 = t * 128;
        float acc[2][8][4];
#pragma unroll
        for (int mt = 0; mt < 2; mt++)
#pragma unroll
            for (int nt = 0; nt < 8; nt++)
#pragma unroll
                for (int q = 0; q < 4; q++) acc[mt][nt][q] = 0.f;

        for (int s = 0; s < 2; s++) {
            const float* X = s ? Xh : Xa;
            __syncthreads();   // prior chunk's LDS done before restage (and B ready)
            // stage + split A chunk [128 rows x 128 bf16]
            for (int it = tid; it < 4096; it += 256) {
                int row = it >> 5, k0 = (it & 31) * 4;
                float4 v = make_float4(0.f, 0.f, 0.f, 0.f);
                int gr = row0 + row;
                if (gr < NN && k0 < KIN)
                    v = *(const float4*)(X + (size_t)gr * KIN + k0);
                __nv_bfloat16 h0 = __float2bfloat16(v.x);
                __nv_bfloat16 h1 = __float2bfloat16(v.y);
                __nv_bfloat16 h2 = __float2bfloat16(v.z);
                __nv_bfloat16 h3 = __float2bfloat16(v.w);
                __nv_bfloat16 l0 = __float2bfloat16(v.x - __bfloat162float(h0));
                __nv_bfloat16 l1 = __float2bfloat16(v.y - __bfloat162float(h1));
                __nv_bfloat16 l2 = __float2bfloat16(v.z - __bfloat162float(h2));
                __nv_bfloat16 l3 = __float2bfloat16(v.w - __bfloat162float(h3));
                uint32_t hA = ((uint32_t)__bfloat16_as_ushort(h1) << 16) | __bfloat16_as_ushort(h0);
                uint32_t hB = ((uint32_t)__bfloat16_as_ushort(h3) << 16) | __bfloat16_as_ushort(h2);
                uint32_t lA = ((uint32_t)__bfloat16_as_ushort(l1) << 16) | __bfloat16_as_ushort(l0);
                uint32_t lB = ((uint32_t)__bfloat16_as_ushort(l3) << 16) | __bfloat16_as_ushort(l2);
                *(uint2*)&sAh[row * SA_STR + k0] = make_uint2(hA, hB);
                *(uint2*)&sAl[row * SA_STR + k0] = make_uint2(lA, lB);
            }
            __syncthreads();

#pragma unroll
            for (int ks = 0; ks < KSTEPS; ks++) {
                const int k0 = ks * 16;
                uint32_t ah[2][4], al[2][4];
#pragma unroll
                for (int mt = 0; mt < 2; mt++) {
                    int r = m0 + mt * 16 + g;
                    int ai = r * (SA_STR / 2) + (k0 >> 1) + tig;
                    ah[mt][0] = uAh[ai];
                    ah[mt][1] = uAh[ai + 8 * (SA_STR / 2)];
                    ah[mt][2] = uAh[ai + 4];
                    ah[mt][3] = uAh[ai + 8 * (SA_STR / 2) + 4];
                    al[mt][0] = uAl[ai];
                    al[mt][1] = uAl[ai + 8 * (SA_STR / 2)];
                    al[mt][2] = uAl[ai + 4];
                    al[mt][3] = uAl[ai + 8 * (SA_STR / 2) + 4];
                }
                const int kg = s * 128 + k0;
#pragma unroll
                for (int nt = 0; nt < 8; nt++) {
                    int c = n0 + nt * 8 + g;
                    int bi = c * (SB_STR / 2) + (kg >> 1) + tig;
                    uint32_t bh0 = uBh[bi], bh1 = uBh[bi + 4];
                    uint32_t bl0 = uBl[bi], bl1 = uBl[bi + 4];
#pragma unroll
                    for (int mt = 0; mt < 2; mt++) {
                        mma16816(acc[mt][nt], ah[mt], bh0, bh1);
                        mma16816(acc[mt][nt], ah[mt], bl0, bl1);
                        mma16816(acc[mt][nt], al[mt], bh0, bh1);
                    }
                }
            }
        }

        // epilogue: bias + activation + store
#pragma unroll
        for (int mt = 0; mt < 2; mt++) {
#pragma unroll
            for (int half = 0; half < 2; half++) {
                int gr = row0 + m0 + mt * 16 + g + half * 8;
                if (gr < NN) {
#pragma unroll
                    for (int nt = 0; nt < 8; nt++) {
                        int c = n0 + nt * 8 + tig * 2;
                        float v0 = acc[mt][nt][half * 2 + 0] + __ldg(bias + c);
                        float v1 = acc[mt][nt][half * 2 + 1] + __ldg(bias + c + 1);
                        if (ACT == 1) {
                            v0 = fmaxf(v0, 0.f); v1 = fmaxf(v1, 0.f);
                        } else if (ACT == 2) {
                            v0 = (v0 > 0.f) ? v0 : 0.01f * v0;
                            v1 = (v1 > 0.f) ? v1 : 0.01f * v1;
                        }
                        *(float2*)(out + (size_t)gr * CH + c) = make_float2(v0, v1);
                    }
                }
            }
        }
    }
}

// ---------------- pooling + head ---------------------------------------------
__global__ void k_pool(const int* __restrict__ batch, const float* __restrict__ h) {
    int idx = blockIdx.x * blockDim.x + threadIdx.x;
    if (idx < NN * CH) {
        int i = idx >> 7;
        int c = idx & 127;
        atomicAdd(&g_gsum[batch[i] * CH + c], h[idx]);
    }
}

__global__ void k_head(const float* __restrict__ headW,
                       const float* __restrict__ headb,
                       float* __restrict__ out) {
    int tid = blockIdx.x * blockDim.x + threadIdx.x;
    if (tid >= GG * COUT) return;
    int g = tid >> 1;
    int o = tid & 1;
    float cnt = (float)g_gcnt[g];
    float inv = 1.f / fmaxf(cnt, 1.f);
    float acc = headb[o];
#pragma unroll 8
    for (int k = 0; k < CH; k++)
        acc += g_gsum[g * CH + k] * inv * headW[k * COUT + o];
    out[tid] = acc;
}

// ---------------- host driver -------------------------------------------------
extern "C" void kernel_launch(void* const* d_in, const int* in_sizes, int n_in,
                              void* d_out, int out_size) {
    const float* x     = (const float*)d_in[0];
    const int*   ei    = (const int*)d_in[1];
    const int*   srcp  = ei;
    const int*   dstp  = ei + EE;
    const int*   batch = (const int*)d_in[2];
    const float* Wl0   = (const float*)d_in[3];
    const float* Wr0   = (const float*)d_in[4];
    const float* b0    = (const float*)d_in[5];
    const float* Wl    = (const float*)d_in[6];
    const float* Wr    = (const float*)d_in[7];
    const float* bb    = (const float*)d_in[8];
    const float* headW = (const float*)d_in[9];
    const float* headb = (const float*)d_in[10];
    float* out = (float*)d_out;

    float *hA, *hB, *agg;
    __nv_bfloat16 *Bhi, *Blo;
    cudaGetSymbolAddress((void**)&hA, g_hA);
    cudaGetSymbolAddress((void**)&hB, g_hB);
    cudaGetSymbolAddress((void**)&agg, g_agg);
    cudaGetSymbolAddress((void**)&Bhi, g_Bhi);
    cudaGetSymbolAddress((void**)&Blo, g_Blo);

    cudaFuncSetAttribute(k_hgemm<64, 1>,  cudaFuncAttributeMaxDynamicSharedMemorySize, SM_TOT);
    cudaFuncSetAttribute(k_hgemm<128, 0>, cudaFuncAttributeMaxDynamicSharedMemorySize, SM_TOT);
    cudaFuncSetAttribute(k_hgemm<128, 1>, cudaFuncAttributeMaxDynamicSharedMemorySize, SM_TOT);
    cudaFuncSetAttribute(k_hgemm<128, 2>, cudaFuncAttributeMaxDynamicSharedMemorySize, SM_TOT);

    // --- graph preprocessing (CSR by dst, graph sizes, weight prep) ---
    k_init<<<256, 256>>>();
    k_count<<<(EE + 255) / 256, 256>>>(dstp);
    k_scan1<<<(NN + 1023) / 1024, 1024>>>();
    k_scan2<<<1, 32>>>((NN + 1023) / 1024);
    k_scan3<<<(NN + 255) / 256, 256>>>();
    k_fill<<<(EE + 255) / 256, 256>>>(srcp, dstp);
    k_gcnt<<<(NN + 255) / 256, 256>>>(batch);
    k_prepw<<<(12 * 32768 + 255) / 256, 256>>>(Wl0, Wr0, Wl, Wr);

    // --- conv 0: C_IN=64 -> 128, ReLU ---
    k_agg<64><<<(NN + 3) / 4, 256>>>(x, agg);
    k_hgemm<64, 1><<<GRID_G, 256, SM_TOT>>>(agg, x, Bhi, Blo, b0, hA);

    // --- convs 1..11 ---
    const int act[11] = {1, 1, 2, 1, 1, 1, 2, 1, 1, 1, 0};
    const float* cur = hA;
    float* nxt = hB;
    for (int li = 0; li < 11; li++) {
        k_agg<128><<<(NN + 1) / 2, 256>>>(cur, agg);
        const __nv_bfloat16* bh = Bhi + (size_t)(li + 1) * 32768;
        const __nv_bfloat16* bl = Blo + (size_t)(li + 1) * 32768;
        const float* bi = bb + (size_t)li * CH;
        if (act[li] == 1)
            k_hgemm<128, 1><<<GRID_G, 256, SM_TOT>>>(agg, cur, bh, bl, bi, nxt);
        else if (act[li] == 2)
            k_hgemm<128, 2><<<GRID_G, 256, SM_TOT>>>(agg, cur, bh, bl, bi, nxt);
        else
            k_hgemm<128, 0><<<GRID_G, 256, SM_TOT>>>(agg, cur, bh, bl, bi, nxt);
        const float* t = cur;
        cur = nxt;
        nxt = (float*)t;
    }

    // --- global mean pool + head ---
    k_pool<<<(NN * CH + 255) / 256, 256>>>(batch, cur);
    k_head<<<(GG * COUT + 255) / 256, 256>>>(headW, headb, out);
}